// round 15
// baseline (speedup 1.0000x reference)
#include <cuda_runtime.h>
#include <cuda_fp16.h>
#include <cstdint>

#define NCV 120000
#define NFV 240000
#define CI128 128
#define CO 64
#define BM 128
#define NB 235
#define FULL 0xffffffffu

// ---------------- scratch (device globals) ---------------------------------
__device__ __half g_xh[(NCV + 1) * CI128];
__device__ float  g_upA[(NCV + 1) * CO];
__device__ __half g_upAh[(NCV + 1) * CO];
__device__ float  g_e1[(NCV + 1) * CO];
__device__ float  g_e2[(NCV + 1) * CO];
__device__ __half g_e1h[(NCV + 1) * CO];
__device__ __half g_e2h[(NCV + 1) * CO];
__device__ float  g_stats[6 * CO];
__device__ float  g_W1s[9 * CO * CO];
__device__ float  g_W2s[9 * CO * CO];
__device__ float  g_Bup[27 * 2 * CO * CO];   // stacked [s1*Wu ; s2*Wu]
__device__ float  g_b1s[9 * CO];
__device__ float  g_b2s[9 * CO];
__device__ float  g_bup[27 * CO];

__constant__ int c_upk[7] = {0, 2, 6, 8, 18, 20, 24};

// ---------------- helpers ---------------------------------------------------
__device__ __forceinline__ void mma_f16(float* d, uint32_t a0, uint32_t a1,
                                        uint32_t a2, uint32_t a3,
                                        uint32_t b0, uint32_t b1) {
    asm volatile(
        "mma.sync.aligned.m16n8k16.row.col.f32.f16.f16.f32 "
        "{%0,%1,%2,%3}, {%4,%5,%6,%7}, {%8,%9}, {%0,%1,%2,%3};"
        : "+f"(d[0]), "+f"(d[1]), "+f"(d[2]), "+f"(d[3])
        : "r"(a0), "r"(a1), "r"(a2), "r"(a3), "r"(b0), "r"(b1));
}
__device__ __forceinline__ void red_add_v2(float* addr, float x, float y) {
    asm volatile("red.global.add.v2.f32 [%0], {%1, %2};"
                 :: "l"(addr), "f"(x), "f"(y) : "memory");
}
__device__ __forceinline__ uint32_t cvta_smem(const void* p) {
    uint32_t a;
    asm("{ .reg .u64 t; cvta.to.shared.u64 t, %1; cvt.u32.u64 %0, t; }" : "=r"(a) : "l"(p));
    return a;
}
__device__ __forceinline__ void cp_async16(uint32_t dst, const void* src) {
    asm volatile("cp.async.ca.shared.global [%0], [%1], 16;" :: "r"(dst), "l"(src));
}
#define CP_COMMIT() asm volatile("cp.async.commit_group;" ::: "memory")
template <int N>
__device__ __forceinline__ void cp_wait() {
    asm volatile("cp.async.wait_group %0;" :: "n"(N) : "memory");
}

// ---------------- MMA building blocks ---------------------------------------
// B smem: permuted half2 rows (one row per k-pair), stride 66 words:
// Bp[kp][(n&7)*8 + (n>>3)] = half2(W[2kp][n], W[2kp+1][n])
template <int CIN>
__device__ __forceinline__ void load_Bh(uint32_t* Bs, const float* Wk, int tid) {
    #pragma unroll
    for (int i = tid; i < (CIN / 2) * 64; i += 256) {
        int n = i & 63, kp = i >> 6;
        float w0 = Wk[(2 * kp) * 64 + n];
        float w1 = Wk[(2 * kp + 1) * 64 + n];
        __half2 h = __floats2half2_rn(w0, w1);
        Bs[kp * 66 + ((n & 7) * 8 + (n >> 3))] = *(uint32_t*)&h;
    }
}

// async gather of one K-half chunk (halves). Row data = KH halves = KH*2 bytes.
// G2: half0 <- f1, half1 <- f2 (rows of KH halves). else: f1 rows of CIN halves.
template <int CIN, bool G2, bool IDENT>
__device__ __forceinline__ void gather_async(uint32_t abase, const __half* f1, const __half* f2,
                                             const int* Si, int p0, int nclamp,
                                             int half_idx, int tid) {
    constexpr int KH = CIN / 2;
    constexpr int U = KH / 8;                 // 16B units per row-chunk (8 or 4)
    constexpr int S = (KH == 64) ? 36 : 20;   // row stride in words
    constexpr int RSTEP = 256 / U;
    const int u = tid & (U - 1);
    const int rr0 = tid / U;
    #pragma unroll
    for (int r = rr0; r < BM; r += RSTEP) {
        int row;
        if (IDENT) { row = p0 + r; if (row > nclamp) row = nclamp; }
        else row = Si[r];
        const __half* src;
        if (G2) src = (half_idx ? f2 : f1) + (size_t)row * KH + u * 8;
        else    src = f1 + (size_t)row * CIN + half_idx * KH + u * 8;
        cp_async16(abase + (uint32_t)(r * S * 4 + u * 16), src);
    }
}

// MMA over one K-half chunk. A half2 words stride S (CTA-wide buffer; warp w
// owns rows 16w..16w+15); Bw points at the weight matrix (k-pair rows, stride
// 66, permuted n).
template <int CIN>
__device__ __forceinline__ void mma16(const uint32_t* Aw, const uint32_t* Bw,
                                      int half_idx, int w, int g, int tig,
                                      float acc[8][4]) {
    constexpr int KH = CIN / 2;
    constexpr int S = (KH == 64) ? 36 : 20;
    const int kb = half_idx * (KH / 2);       // k-pair row base of this chunk
    const uint32_t* r0 = Aw + (16 * w + g) * S;
    const uint32_t* r1 = Aw + (16 * w + g + 8) * S;
    #pragma unroll
    for (int ks = 0; ks < KH / 16; ks++) {
        const int kw = ks * 8;
        uint32_t a0 = r0[kw + tig];
        uint32_t a1 = r1[kw + tig];
        uint32_t a2 = r0[kw + tig + 4];
        uint32_t a3 = r1[kw + tig + 4];
        const uint2* b0p = (const uint2*)(Bw + (kb + kw + tig) * 66 + g * 8);
        const uint2* b1p = (const uint2*)(Bw + (kb + kw + tig + 4) * 66 + g * 8);
        #pragma unroll
        for (int c2 = 0; c2 < 4; c2++) {
            uint2 u0 = b0p[c2], u1 = b1p[c2];
            mma_f16(acc[2 * c2],     a0, a1, a2, a3, u0.x, u1.x);
            mma_f16(acc[2 * c2 + 1], a0, a1, a2, a3, u0.y, u1.y);
        }
    }
}

__device__ __forceinline__ void acc_zero(float acc[8][4]) {
    #pragma unroll
    for (int c = 0; c < 8; c++) { acc[c][0] = acc[c][1] = acc[c][2] = acc[c][3] = 0.f; }
}
// bias applied at epilogue from smem (keeps registers low during mainloop)
__device__ __forceinline__ void apply_bias_smem(float acc[8][4], const float* bS, int tig) {
    #pragma unroll
    for (int c = 0; c < 8; c++) {
        float2 b = *(const float2*)(bS + 8 * c + 2 * tig);
        acc[c][0] += b.x; acc[c][1] += b.y;
        acc[c][2] += b.x; acc[c][3] += b.y;
    }
}
__device__ __forceinline__ void scatter_add(float* out, int o, int tig,
                                            const float acc[8][4], int half) {
    float* d = out + (size_t)o * CO + 2 * tig;
    #pragma unroll
    for (int c = 0; c < 8; c++) red_add_v2(d + 8 * c, acc[c][2 * half], acc[c][2 * half + 1]);
}
__device__ __forceinline__ void scatter_st(float* out, int o, int tig,
                                           const float acc[8][4], int half) {
    float2* d = (float2*)(out + (size_t)o * CO + 2 * tig);
    #pragma unroll
    for (int c = 0; c < 8; c++) d[4 * c] = make_float2(acc[c][2 * half], acc[c][2 * half + 1]);
}

// ---------------- center kernel: identity rows, plain stores, pipelined -----
template <int CIN, int NW, int T, bool G2, int MINB>
__global__ __launch_bounds__(256, MINB) void spmm_center(
    const __half* __restrict__ f1, const __half* __restrict__ f2,
    const float* __restrict__ W0, const float* __restrict__ W1b,
    const float* __restrict__ bias0, const float* __restrict__ bias1,
    float* __restrict__ out0, float* __restrict__ out1, int n)
{
    constexpr int KH = CIN / 2;
    constexpr int S = (KH == 64) ? 36 : 20;
    constexpr int BW = (CIN / 2) * 66;       // words per weight matrix
    extern __shared__ uint32_t sm[];
    uint32_t* A0 = sm;
    uint32_t* A1 = A0 + BM * S;
    uint32_t* Bs = A1 + BM * S;
    float* biasS = (float*)(Bs + NW * BW);
    const int tid = threadIdx.x;
    const uint32_t a0b = cvta_smem(A0), a1b = cvta_smem(A1);
    const int w = tid >> 5, lane = tid & 31, g = lane >> 2, tig = lane & 3;

    load_Bh<CIN>(Bs, W0, tid);
    if (NW == 2) load_Bh<CIN>(Bs + BW, W1b, tid);
    if (tid < 64) biasS[tid] = bias0 ? bias0[tid] : 0.f;
    if (NW == 2 && tid >= 64 && tid < 128) biasS[tid] = bias1 ? bias1[tid - 64] : 0.f;

    int p0 = blockIdx.x * T * BM;
    if (p0 >= n) return;
    gather_async<CIN, G2, true>(a0b, f1, f2, nullptr, p0, n, 0, tid); CP_COMMIT();
    gather_async<CIN, G2, true>(a1b, f1, f2, nullptr, p0, n, 1, tid); CP_COMMIT();

    for (int t = 0; ; t++) {
        int p0n = p0 + BM;
        bool nxt = (t + 1 < T) && (p0n < n);
        cp_wait<1>(); __syncthreads();
        float acc[8][4], accB[8][4];
        acc_zero(acc);
        mma16<CIN>(A0, Bs, 0, w, g, tig, acc);
        if (NW == 2) { acc_zero(accB); mma16<CIN>(A0, Bs + BW, 0, w, g, tig, accB); }
        __syncthreads();
        if (nxt) {
            gather_async<CIN, G2, true>(a0b, f1, f2, nullptr, p0n, n, 0, tid); CP_COMMIT();
            cp_wait<1>();
        } else cp_wait<0>();
        __syncthreads();
        mma16<CIN>(A1, Bs, 1, w, g, tig, acc);
        if (NW == 2) mma16<CIN>(A1, Bs + BW, 1, w, g, tig, accB);
        __syncthreads();
        if (nxt) { gather_async<CIN, G2, true>(a1b, f1, f2, nullptr, p0n, n, 1, tid); CP_COMMIT(); }
        apply_bias_smem(acc, biasS, tig);
        int r0 = p0 + 16 * w + g;
        if (r0 < n) scatter_st(out0, r0, tig, acc, 0);
        if (r0 + 8 < n) scatter_st(out0, r0 + 8, tig, acc, 1);
        if (NW == 2) {
            apply_bias_smem(accB, biasS + 64, tig);
            if (r0 < n) scatter_st(out1, r0, tig, accB, 0);
            if (r0 + 8 < n) scatter_st(out1, r0 + 8, tig, accB, 1);
        }
        if (!nxt) return;
        p0 = p0n;
    }
}

// ---------------- rest body: pair gather, atomic scatter, pipelined ---------
template <int CIN, int T, bool G2>
__device__ __forceinline__ void rest_body(
    const __half* __restrict__ f1, const __half* __restrict__ f2,
    const int* __restrict__ pairs, long long pbase,
    const float* __restrict__ Wk, const float* __restrict__ biask,
    float* __restrict__ out, int P, int n_out, int n_zero)
{
    constexpr int KH = CIN / 2;
    constexpr int S = (KH == 64) ? 36 : 20;
    extern __shared__ uint32_t sm[];
    int* Si = (int*)sm;                 // [2][BM]
    int* So = Si + 2 * BM;              // [2][BM]
    uint32_t* A0 = (uint32_t*)(So + 2 * BM);
    uint32_t* A1 = A0 + BM * S;
    uint32_t* Bs = A1 + BM * S;
    float* biasS = (float*)(Bs + (CIN / 2) * 66);
    const int tid = threadIdx.x;
    const uint32_t a0b = cvta_smem(A0), a1b = cvta_smem(A1);
    const int w = tid >> 5, lane = tid & 31, g = lane >> 2, tig = lane & 3;

    int p0 = blockIdx.x * T * BM;
    if (p0 >= P) return;
    if (pairs[(pbase + p0) * 2 + 1] >= n_out) return;  // prefix early-exit

    load_Bh<CIN>(Bs, Wk, tid);
    if (tid < 64) biasS[tid] = biask ? biask[tid] : 0.f;

    if (tid < BM) {
        int p = p0 + tid;
        if (p < P) {
            const int* pr = pairs + (pbase + p) * 2;
            Si[tid] = pr[0]; So[tid] = pr[1];
        } else { Si[tid] = n_zero; So[tid] = n_out; }
    }
    __syncthreads();
    gather_async<CIN, G2, false>(a0b, f1, f2, Si, 0, 0, 0, tid); CP_COMMIT();
    gather_async<CIN, G2, false>(a1b, f1, f2, Si, 0, 0, 1, tid); CP_COMMIT();

    int buf = 0;
    for (int t = 0; ; t++) {
        // hoist current tile's out-indices before any index-buffer overwrite
        const int* Sob = So + buf * BM;
        const int o0 = Sob[16 * w + g];
        const int o1 = Sob[16 * w + g + 8];

        int p0n = p0 + BM;
        bool nxt = (t + 1 < T) && (p0n < P) && (pairs[(pbase + p0n) * 2 + 1] < n_out);
        if (nxt && tid < BM) {
            int p = p0n + tid;
            int* Si2 = Si + (buf ^ 1) * BM;
            int* So2 = So + (buf ^ 1) * BM;
            if (p < P) {
                const int* pr = pairs + (pbase + p) * 2;
                Si2[tid] = pr[0]; So2[tid] = pr[1];
            } else { Si2[tid] = n_zero; So2[tid] = n_out; }
        }
        cp_wait<1>(); __syncthreads();
        float acc[8][4];
        acc_zero(acc);
        mma16<CIN>(A0, Bs, 0, w, g, tig, acc);
        __syncthreads();
        if (nxt) {
            gather_async<CIN, G2, false>(a0b, f1, f2, Si + (buf ^ 1) * BM, 0, 0, 0, tid);
            CP_COMMIT();
            cp_wait<1>();
        } else cp_wait<0>();
        __syncthreads();
        mma16<CIN>(A1, Bs, 1, w, g, tig, acc);
        __syncthreads();
        if (nxt) {
            gather_async<CIN, G2, false>(a1b, f1, f2, Si + (buf ^ 1) * BM, 0, 0, 1, tid);
            CP_COMMIT();
        }
        apply_bias_smem(acc, biasS, tig);
        if (o0 < n_out) scatter_add(out, o0, tig, acc, 0);
        if (o1 < n_out) scatter_add(out, o1, tig, acc, 1);
        if (!nxt) return;
        buf ^= 1; p0 = p0n;
    }
}

template <int CIN, int T, bool G2, bool UPMAP>
__global__ __launch_bounds__(256, 4) void spmm_rest(
    const __half* __restrict__ f1, const __half* __restrict__ f2,
    const int* __restrict__ pairs, const float* __restrict__ W,
    const float* __restrict__ bias, float* __restrict__ out,
    int P, int n_out, int n_zero, int kskip)
{
    int ky = blockIdx.y;
    int k = UPMAP ? c_upk[ky] : ((kskip >= 0 && ky >= kskip) ? ky + 1 : ky);
    rest_body<CIN, T, G2>(f1, f2, pairs, (long long)k * P,
                          W + (size_t)k * CIN * CO,
                          bias ? bias + k * CO : nullptr,
                          out, P, n_out, n_zero);
}

// merged conv13-rest + conv31-rest (grid.y = 16)
template <int T>
__global__ __launch_bounds__(256, 4) void spmm_rest2(
    const __half* __restrict__ f1,
    const int* __restrict__ pA, const int* __restrict__ pB,
    const float* __restrict__ WA, const float* __restrict__ WB,
    const float* __restrict__ bA, const float* __restrict__ bB,
    float* __restrict__ oA, float* __restrict__ oB,
    int P, int n_out, int n_zero)
{
    int ky = blockIdx.y;
    bool first = ky < 8;
    int kk = ky & 7;
    int k = kk + (kk >= 4);   // skip center offset 4
    rest_body<CO, T, false>(f1, nullptr, first ? pA : pB, (long long)k * P,
                            (first ? WA : WB) + (size_t)k * CO * CO,
                            (first ? bA : bB) + k * CO,
                            first ? oA : oB, P, n_out, n_zero);
}

// ---------------- elementwise / prep -----------------------------------------
__global__ void k_add_h(const float4* __restrict__ a, const float4* __restrict__ b,
                        __half2* __restrict__ o, int n4) {
    for (int i = blockIdx.x * blockDim.x + threadIdx.x; i < n4; i += gridDim.x * blockDim.x) {
        float4 x = a[i], y = b[i];
        o[2 * i]     = __floats2half2_rn(x.x + y.x, x.y + y.y);
        o[2 * i + 1] = __floats2half2_rn(x.z + y.z, x.w + y.w);
    }
}

__global__ void k_stats_act(const float* __restrict__ buf, __half* __restrict__ outh,
                            float* __restrict__ stats, int n) {
    __shared__ float ss[CO], sq[CO];
    int tid = threadIdx.x;
    if (tid < CO) { ss[tid] = 0.f; sq[tid] = 0.f; }
    __syncthreads();
    float s = 0.f, q = 0.f;
    int c = tid & (CO - 1);
    int total = n * CO;
    for (int idx = blockIdx.x * blockDim.x + tid; idx < total; idx += gridDim.x * blockDim.x) {
        float v = buf[idx];
        v = (v > 0.f) ? v : 0.01f * v;
        outh[idx] = __float2half_rn(v);
        s += v; q += v * v;
    }
    atomicAdd(&ss[c], s);
    atomicAdd(&sq[c], q);
    __syncthreads();
    if (tid < CO) {
        atomicAdd(&stats[tid], ss[tid]);
        atomicAdd(&stats[CO + tid], sq[tid]);
    }
}

__global__ void k_stats2(const float* __restrict__ e1, const float* __restrict__ e2,
                         __half* __restrict__ e1h, __half* __restrict__ e2h,
                         float* __restrict__ stats, int n) {
    __shared__ float s[4 * CO];
    int tid = threadIdx.x;
    for (int i = tid; i < 4 * CO; i += 256) s[i] = 0.f;
    __syncthreads();
    float s1 = 0.f, q1 = 0.f, s2 = 0.f, q2 = 0.f;
    int c = tid & (CO - 1);
    int total = n * CO;
    for (int idx = blockIdx.x * blockDim.x + tid; idx < total; idx += gridDim.x * blockDim.x) {
        float v1 = e1[idx], v2 = e2[idx];
        e1h[idx] = __float2half_rn(v1);
        e2h[idx] = __float2half_rn(v2);
        s1 += v1; q1 += v1 * v1;
        s2 += v2; q2 += v2 * v2;
    }
    atomicAdd(&s[c], s1);
    atomicAdd(&s[CO + c], q1);
    atomicAdd(&s[2 * CO + c], s2);
    atomicAdd(&s[3 * CO + c], q2);
    __syncthreads();
    if (tid < CO) {
        atomicAdd(&stats[2 * CO + tid], s[tid]);
        atomicAdd(&stats[3 * CO + tid], s[CO + tid]);
        atomicAdd(&stats[4 * CO + tid], s[2 * CO + tid]);
        atomicAdd(&stats[5 * CO + tid], s[3 * CO + tid]);
    }
}

// fused finalize + fold for BOTH W1 and W2 in one launch (18 blocks):
// block k<9 -> W1 -> W1s/b1s ; block k>=9 -> W2 -> W2s/b2s
__global__ void k_prep2(const float* __restrict__ W1, const float* __restrict__ W2,
                        const float* __restrict__ stats,
                        const float* __restrict__ g, const float* __restrict__ b,
                        float* __restrict__ W1s, float* __restrict__ W2s,
                        float* __restrict__ b1s, float* __restrict__ b2s, float invN) {
    int blk = blockIdx.x;
    bool first = blk < 9;
    int k = first ? blk : blk - 9;
    const float* W = first ? W1 : W2;
    float* Ws = first ? W1s : W2s;
    float* bias = first ? b1s : b2s;
    int tid = threadIdx.x;
    __shared__ float sc[64], off[64];
    __shared__ float pb[4][64];
    if (tid < 64) {
        float mean = stats[tid] * invN;
        float var  = stats[CO + tid] * invN - mean * mean;
        float s = g[tid] * rsqrtf(var + 1e-5f);
        sc[tid] = s;
        off[tid] = b[tid] - mean * s;
    }
    __syncthreads();
    const float* Wk = W + (size_t)k * 4096;
    float* Wsk = Ws + (size_t)k * 4096;
    float acc = 0.f;
    int n = tid & 63, cg = tid >> 6;
    #pragma unroll
    for (int cc = 0; cc < 16; cc++) {
        int c = cg * 16 + cc;
        float wv = Wk[c * 64 + n];
        Wsk[c * 64 + n] = sc[c] * wv;
        acc += off[c] * wv;
    }
    pb[cg][n] = acc;
    __syncthreads();
    if (tid < 64) bias[k * 64 + tid] = pb[0][tid] + pb[1][tid] + pb[2][tid] + pb[3][tid];
}

// fused finalize2 + upsample fold (layers 1,2 from stats[128..383]).
// RACE-FREE: per-layer offsets go to disjoint arrays, summed after the sync.
__global__ void k_prep_up(const float* __restrict__ Wu, const float* __restrict__ stats,
                          const float* __restrict__ g1, const float* __restrict__ b1,
                          const float* __restrict__ g2, const float* __restrict__ b2,
                          float* __restrict__ Bst, float* __restrict__ bias, float invN) {
    int k = blockIdx.x;
    int tid = threadIdx.x;
    __shared__ float sc1[64], sc2[64], off1[64], off2[64];
    __shared__ float pb[4][64];
    if (tid < 128) {
        int layer = tid >> 6, c = tid & 63;
        const float* st = stats + (1 + layer) * 2 * CO;
        float mean = st[c] * invN;
        float var  = st[CO + c] * invN - mean * mean;
        float s = (layer ? g2[c] : g1[c]) * rsqrtf(var + 1e-5f);
        float o = (layer ? b2[c] : b1[c]) - mean * s;
        if (layer) { sc2[c] = s; off2[c] = o; }
        else       { sc1[c] = s; off1[c] = o; }
    }
    __syncthreads();
    const float* Wk = Wu + (size_t)k * 4096;
    float* Bk = Bst + (size_t)k * 8192;
    float acc = 0.f;
    int n = tid & 63, cg = tid >> 6;
    #pragma unroll
    for (int cc = 0; cc < 16; cc++) {
        int c = cg * 16 + cc;
        float wv = Wk[c * 64 + n];
        Bk[c * 64 + n] = sc1[c] * wv;
        Bk[4096 + c * 64 + n] = sc2[c] * wv;
        acc += (off1[c] + off2[c]) * wv;
    }
    pb[cg][n] = acc;
    __syncthreads();
    if (tid < 64) bias[k * 64 + tid] = pb[0][tid] + pb[1][tid] + pb[2][tid] + pb[3][tid];
}

__global__ void k_dummy() {}

// ---------------- launch ------------------------------------------------------
extern "C" void kernel_launch(void* const* d_in, const int* in_sizes, int n_in,
                              void* d_out, int out_size) {
    const float* fx  = (const float*)d_in[0];
    const float* fs  = (const float*)d_in[1];
    const float* Wt  = (const float*)d_in[2];
    const float* W1  = (const float*)d_in[3];
    const float* W2  = (const float*)d_in[4];
    const float* Wu  = (const float*)d_in[5];
    const float* g0  = (const float*)d_in[6];
    const float* b0  = (const float*)d_in[7];
    const float* g1  = (const float*)d_in[8];
    const float* b1  = (const float*)d_in[9];
    const float* g2  = (const float*)d_in[10];
    const float* b2  = (const float*)d_in[11];
    const int*   p33 = (const int*)d_in[12];
    const int*   p13 = (const int*)d_in[13];
    const int*   p31 = (const int*)d_in[14];
    const int*   pup = (const int*)d_in[15];
    float* outp = (float*)d_out;

    __half *xh, *upAh, *e1h, *e2h;
    float *upA, *e1, *e2, *stats, *w1s, *w2s, *bup, *b1s, *b2s, *bupb;
    cudaGetSymbolAddress((void**)&xh,    g_xh);
    cudaGetSymbolAddress((void**)&upA,   g_upA);
    cudaGetSymbolAddress((void**)&upAh,  g_upAh);
    cudaGetSymbolAddress((void**)&e1,    g_e1);
    cudaGetSymbolAddress((void**)&e2,    g_e2);
    cudaGetSymbolAddress((void**)&e1h,   g_e1h);
    cudaGetSymbolAddress((void**)&e2h,   g_e2h);
    cudaGetSymbolAddress((void**)&stats, g_stats);
    cudaGetSymbolAddress((void**)&w1s,   g_W1s);
    cudaGetSymbolAddress((void**)&w2s,   g_W2s);
    cudaGetSymbolAddress((void**)&bup,   g_Bup);
    cudaGetSymbolAddress((void**)&b1s,   g_b1s);
    cudaGetSymbolAddress((void**)&b2s,   g_b2s);
    cudaGetSymbolAddress((void**)&bupb,  g_bup);

    // smem bytes: A = 2*BM*S, B = NW*(CIN/2)*66, bias NW*64, rest adds 4*BM idx
    const int SM_R128  = (4 * BM + 2 * BM * 36 + 64 * 66 + 64) * 4;   // 56064
    const int SM_R64   = (4 * BM + 2 * BM * 20 + 32 * 66 + 64) * 4;   // 31232
    const int SM_C128  = (2 * BM * 36 + 64 * 66 + 64) * 4;            // 54016
    const int SM_C64x2 = (2 * BM * 20 + 2 * 32 * 66 + 128) * 4;       // 37888
    const int SM_UP    = (2 * BM * 36 + 2 * 64 * 66 + 128) * 4;       // 71168

    cudaFuncSetAttribute((const void*)spmm_center<CI128, 1, 4, false, 4>, cudaFuncAttributeMaxDynamicSharedMemorySize, SM_C128);
    cudaFuncSetAttribute((const void*)spmm_rest<CI128, 4, false, false>, cudaFuncAttributeMaxDynamicSharedMemorySize, SM_R128);
    cudaFuncSetAttribute((const void*)spmm_center<CO, 2, 4, false, 4>, cudaFuncAttributeMaxDynamicSharedMemorySize, SM_C64x2);
    cudaFuncSetAttribute((const void*)spmm_rest2<4>, cudaFuncAttributeMaxDynamicSharedMemorySize, SM_R64);
    cudaFuncSetAttribute((const void*)spmm_center<CI128, 2, 4, true, 3>, cudaFuncAttributeMaxDynamicSharedMemorySize, SM_UP);
    cudaFuncSetAttribute((const void*)spmm_rest<CI128, 4, true, true>, cudaFuncAttributeMaxDynamicSharedMemorySize, SM_R128);

    cudaMemsetAsync(stats, 0, 6 * CO * sizeof(float));

    // (1) xh = fp16(feats_x + feats_skip)
    k_add_h<<<2048, 256>>>((const float4*)fx, (const float4*)fs, (__half2*)xh, NCV * CI128 / 4);

    // (2) conv1 center: upA = xh @ Wt[13] (plain stores; rest adds after)
    spmm_center<CI128, 1, 4, false, 4><<<NB, 256, SM_C128>>>(
        xh, nullptr, Wt + (size_t)13 * CI128 * CO, nullptr, nullptr, nullptr,
        upA, nullptr, NCV);

    // (3) dummy — keeps conv1-rest at ncu capture slot #4
    k_dummy<<<1, 32>>>();

    // (4) conv1 rest: 26 offsets atomic into upA
    spmm_rest<CI128, 4, false, false><<<dim3(NB, 26), 256, SM_R128>>>(
        xh, nullptr, p33, Wt, nullptr, upA, NCV, NCV, NCV, 13);

    // (5) leaky + stats -> upAh
    k_stats_act<<<1024, 256>>>(upA, upAh, stats, NCV);

    // (6) fused finalize+fold bn0 into W1 AND W2 (one launch)
    k_prep2<<<18, 256>>>(W1, W2, stats, g0, b0, w1s, w2s, b1s, b2s, 1.0f / NCV);

    // (7) conv13/31 centers: e1 = upAh @ W1s[4] + b1s[4]; e2 likewise
    spmm_center<CO, 2, 4, false, 4><<<NB, 256, SM_C64x2>>>(
        upAh, nullptr, w1s + (size_t)4 * CO * CO, w2s + (size_t)4 * CO * CO,
        b1s + 4 * CO, b2s + 4 * CO, e1, e2, NCV);

    // (8) conv13/31 rest merged (16 jobs)
    spmm_rest2<4><<<dim3(NB, 16), 256, SM_R64>>>(
        upAh, p13, p31, w1s, w2s, b1s, b2s, e1, e2, NCV, NCV, NCV);

    // (9) e1/e2 stats -> e1h/e2h
    k_stats2<<<1024, 256>>>(e1, e2, e1h, e2h, stats, NCV);

    // (10) fused finalize2 + fold bn1/bn2 into stacked upsample weights
    k_prep_up<<<27, 256>>>(Wu, stats, g1, b1, g2, b2, bup, bupb, 1.0f / NCV);

    // (11) upsample identity offsets 13 & 26: dense stores covering all of d_out
    spmm_center<CI128, 2, 4, true, 3><<<NB, 256, SM_UP>>>(
        e1h, e2h, bup + (size_t)13 * 8192, bup + (size_t)26 * 8192,
        bupb + 13 * CO, bupb + 26 * CO, outp, outp + (size_t)NCV * CO, NCV);

    // (12) upsample: the 7 possibly-nonempty sparse offsets, atomic into d_out
    spmm_rest<CI128, 4, true, true><<<dim3(NB, 7), 256, SM_R128>>>(
        e1h, e2h, pup, bup, bupb, outp, NCV, NFV, NCV, 0);
}

// round 16
// speedup vs baseline: 1.0520x; 1.0520x over previous
#include <cuda_runtime.h>
#include <cuda_fp16.h>
#include <cstdint>

#define NCV 120000
#define NFV 240000
#define CI128 128
#define CO 64
#define BM 128
#define NB 235
#define FULL 0xffffffffu

// ---------------- scratch (device globals) ---------------------------------
__device__ __half g_xh[(NCV + 1) * CI128];
__device__ float  g_upA[(NCV + 1) * CO];
__device__ __half g_upAh[(NCV + 1) * CO];
__device__ float  g_e1[(NCV + 1) * CO];
__device__ float  g_e2[(NCV + 1) * CO];
__device__ __half g_e1h[(NCV + 1) * CO];
__device__ __half g_e2h[(NCV + 1) * CO];
__device__ float  g_stats[6 * CO];
__device__ float  g_W1s[9 * CO * CO];
__device__ float  g_W2s[9 * CO * CO];
__device__ float  g_Bup[27 * 2 * CO * CO];   // stacked [s1*Wu ; s2*Wu]
__device__ float  g_b1s[9 * CO];
__device__ float  g_b2s[9 * CO];
__device__ float  g_bup[27 * CO];

__constant__ int c_upk[7] = {0, 2, 6, 8, 18, 20, 24};

// ---------------- helpers ---------------------------------------------------
__device__ __forceinline__ void mma_f16(float* d, uint32_t a0, uint32_t a1,
                                        uint32_t a2, uint32_t a3,
                                        uint32_t b0, uint32_t b1) {
    asm volatile(
        "mma.sync.aligned.m16n8k16.row.col.f32.f16.f16.f32 "
        "{%0,%1,%2,%3}, {%4,%5,%6,%7}, {%8,%9}, {%0,%1,%2,%3};"
        : "+f"(d[0]), "+f"(d[1]), "+f"(d[2]), "+f"(d[3])
        : "r"(a0), "r"(a1), "r"(a2), "r"(a3), "r"(b0), "r"(b1));
}
__device__ __forceinline__ void red_add_v2(float* addr, float x, float y) {
    asm volatile("red.global.add.v2.f32 [%0], {%1, %2};"
                 :: "l"(addr), "f"(x), "f"(y) : "memory");
}
__device__ __forceinline__ uint32_t cvta_smem(const void* p) {
    uint32_t a;
    asm("{ .reg .u64 t; cvta.to.shared.u64 t, %1; cvt.u32.u64 %0, t; }" : "=r"(a) : "l"(p));
    return a;
}
__device__ __forceinline__ void cp_async16(uint32_t dst, const void* src) {
    asm volatile("cp.async.ca.shared.global [%0], [%1], 16;" :: "r"(dst), "l"(src));
}
#define CP_COMMIT() asm volatile("cp.async.commit_group;" ::: "memory")
template <int N>
__device__ __forceinline__ void cp_wait() {
    asm volatile("cp.async.wait_group %0;" :: "n"(N) : "memory");
}

// ---------------- MMA building blocks ---------------------------------------
// B smem: permuted half2 rows (one row per k-pair), stride 66 words:
// Bp[kp][(n&7)*8 + (n>>3)] = half2(W[2kp][n], W[2kp+1][n])
template <int CIN>
__device__ __forceinline__ void load_Bh(uint32_t* Bs, const float* Wk, int tid) {
    #pragma unroll
    for (int i = tid; i < (CIN / 2) * 64; i += 256) {
        int n = i & 63, kp = i >> 6;
        float w0 = Wk[(2 * kp) * 64 + n];
        float w1 = Wk[(2 * kp + 1) * 64 + n];
        __half2 h = __floats2half2_rn(w0, w1);
        Bs[kp * 66 + ((n & 7) * 8 + (n >> 3))] = *(uint32_t*)&h;
    }
}

// async gather of one K-half chunk (halves). Row data = KH halves = KH*2 bytes.
// G2: half0 <- f1, half1 <- f2 (rows of KH halves). else: f1 rows of CIN halves.
template <int CIN, bool G2, bool IDENT>
__device__ __forceinline__ void gather_async(uint32_t abase, const __half* f1, const __half* f2,
                                             const int* Si, int p0, int nclamp,
                                             int half_idx, int tid) {
    constexpr int KH = CIN / 2;
    constexpr int U = KH / 8;                 // 16B units per row-chunk (8 or 4)
    constexpr int S = (KH == 64) ? 36 : 20;   // row stride in words
    constexpr int RSTEP = 256 / U;
    const int u = tid & (U - 1);
    const int rr0 = tid / U;
    #pragma unroll
    for (int r = rr0; r < BM; r += RSTEP) {
        int row;
        if (IDENT) { row = p0 + r; if (row > nclamp) row = nclamp; }
        else row = Si[r];
        const __half* src;
        if (G2) src = (half_idx ? f2 : f1) + (size_t)row * KH + u * 8;
        else    src = f1 + (size_t)row * CIN + half_idx * KH + u * 8;
        cp_async16(abase + (uint32_t)(r * S * 4 + u * 16), src);
    }
}

// MMA over one K-half chunk. A half2 words stride S (CTA-wide buffer; warp w
// owns rows 16w..16w+15); Bw points at the weight matrix (k-pair rows, stride
// 66, permuted n).
template <int CIN>
__device__ __forceinline__ void mma16(const uint32_t* Aw, const uint32_t* Bw,
                                      int half_idx, int w, int g, int tig,
                                      float acc[8][4]) {
    constexpr int KH = CIN / 2;
    constexpr int S = (KH == 64) ? 36 : 20;
    const int kb = half_idx * (KH / 2);       // k-pair row base of this chunk
    const uint32_t* r0 = Aw + (16 * w + g) * S;
    const uint32_t* r1 = Aw + (16 * w + g + 8) * S;
    #pragma unroll
    for (int ks = 0; ks < KH / 16; ks++) {
        const int kw = ks * 8;
        uint32_t a0 = r0[kw + tig];
        uint32_t a1 = r1[kw + tig];
        uint32_t a2 = r0[kw + tig + 4];
        uint32_t a3 = r1[kw + tig + 4];
        const uint2* b0p = (const uint2*)(Bw + (kb + kw + tig) * 66 + g * 8);
        const uint2* b1p = (const uint2*)(Bw + (kb + kw + tig + 4) * 66 + g * 8);
        #pragma unroll
        for (int c2 = 0; c2 < 4; c2++) {
            uint2 u0 = b0p[c2], u1 = b1p[c2];
            mma_f16(acc[2 * c2],     a0, a1, a2, a3, u0.x, u1.x);
            mma_f16(acc[2 * c2 + 1], a0, a1, a2, a3, u0.y, u1.y);
        }
    }
}

__device__ __forceinline__ void acc_zero(float acc[8][4]) {
    #pragma unroll
    for (int c = 0; c < 8; c++) { acc[c][0] = acc[c][1] = acc[c][2] = acc[c][3] = 0.f; }
}
// bias applied at epilogue from smem (keeps registers low during mainloop)
__device__ __forceinline__ void apply_bias_smem(float acc[8][4], const float* bS, int tig) {
    #pragma unroll
    for (int c = 0; c < 8; c++) {
        float2 b = *(const float2*)(bS + 8 * c + 2 * tig);
        acc[c][0] += b.x; acc[c][1] += b.y;
        acc[c][2] += b.x; acc[c][3] += b.y;
    }
}
__device__ __forceinline__ void scatter_add(float* out, int o, int tig,
                                            const float acc[8][4], int half) {
    float* d = out + (size_t)o * CO + 2 * tig;
    #pragma unroll
    for (int c = 0; c < 8; c++) red_add_v2(d + 8 * c, acc[c][2 * half], acc[c][2 * half + 1]);
}
__device__ __forceinline__ void scatter_st(float* out, int o, int tig,
                                           const float acc[8][4], int half) {
    float2* d = (float2*)(out + (size_t)o * CO + 2 * tig);
    #pragma unroll
    for (int c = 0; c < 8; c++) d[4 * c] = make_float2(acc[c][2 * half], acc[c][2 * half + 1]);
}

// ---------------- center kernel: identity rows, plain stores, pipelined -----
template <int CIN, int NW, int T, bool G2>
__global__ __launch_bounds__(256, (NW == 1) ? 4 : 2) void spmm_center(
    const __half* __restrict__ f1, const __half* __restrict__ f2,
    const float* __restrict__ W0, const float* __restrict__ W1b,
    const float* __restrict__ bias0, const float* __restrict__ bias1,
    float* __restrict__ out0, float* __restrict__ out1, int n)
{
    constexpr int KH = CIN / 2;
    constexpr int S = (KH == 64) ? 36 : 20;
    constexpr int BW = (CIN / 2) * 66;       // words per weight matrix
    extern __shared__ uint32_t sm[];
    uint32_t* A0 = sm;
    uint32_t* A1 = A0 + BM * S;
    uint32_t* Bs = A1 + BM * S;
    float* biasS = (float*)(Bs + NW * BW);
    const int tid = threadIdx.x;
    const uint32_t a0b = cvta_smem(A0), a1b = cvta_smem(A1);
    const int w = tid >> 5, lane = tid & 31, g = lane >> 2, tig = lane & 3;

    load_Bh<CIN>(Bs, W0, tid);
    if (NW == 2) load_Bh<CIN>(Bs + BW, W1b, tid);
    if (tid < 64) biasS[tid] = bias0 ? bias0[tid] : 0.f;
    if (NW == 2 && tid >= 64 && tid < 128) biasS[tid] = bias1 ? bias1[tid - 64] : 0.f;

    int p0 = blockIdx.x * T * BM;
    if (p0 >= n) return;
    gather_async<CIN, G2, true>(a0b, f1, f2, nullptr, p0, n, 0, tid); CP_COMMIT();
    gather_async<CIN, G2, true>(a1b, f1, f2, nullptr, p0, n, 1, tid); CP_COMMIT();

    for (int t = 0; ; t++) {
        int p0n = p0 + BM;
        bool nxt = (t + 1 < T) && (p0n < n);
        cp_wait<1>(); __syncthreads();
        float acc[8][4], accB[8][4];
        acc_zero(acc);
        mma16<CIN>(A0, Bs, 0, w, g, tig, acc);
        if (NW == 2) { acc_zero(accB); mma16<CIN>(A0, Bs + BW, 0, w, g, tig, accB); }
        __syncthreads();
        if (nxt) {
            gather_async<CIN, G2, true>(a0b, f1, f2, nullptr, p0n, n, 0, tid); CP_COMMIT();
            cp_wait<1>();
        } else cp_wait<0>();
        __syncthreads();
        mma16<CIN>(A1, Bs, 1, w, g, tig, acc);
        if (NW == 2) mma16<CIN>(A1, Bs + BW, 1, w, g, tig, accB);
        __syncthreads();
        if (nxt) { gather_async<CIN, G2, true>(a1b, f1, f2, nullptr, p0n, n, 1, tid); CP_COMMIT(); }
        apply_bias_smem(acc, biasS, tig);
        int r0 = p0 + 16 * w + g;
        if (r0 < n) scatter_st(out0, r0, tig, acc, 0);
        if (r0 + 8 < n) scatter_st(out0, r0 + 8, tig, acc, 1);
        if (NW == 2) {
            apply_bias_smem(accB, biasS + 64, tig);
            if (r0 < n) scatter_st(out1, r0, tig, accB, 0);
            if (r0 + 8 < n) scatter_st(out1, r0 + 8, tig, accB, 1);
        }
        if (!nxt) return;
        p0 = p0n;
    }
}

// ---------------- rest body: pair gather, atomic scatter, pipelined ---------
template <int CIN, int T, bool G2>
__device__ __forceinline__ void rest_body(
    const __half* __restrict__ f1, const __half* __restrict__ f2,
    const int* __restrict__ pairs, long long pbase,
    const float* __restrict__ Wk, const float* __restrict__ biask,
    float* __restrict__ out, int P, int n_out, int n_zero)
{
    constexpr int KH = CIN / 2;
    constexpr int S = (KH == 64) ? 36 : 20;
    extern __shared__ uint32_t sm[];
    int* Si = (int*)sm;                 // [2][BM]
    int* So = Si + 2 * BM;              // [2][BM]
    uint32_t* A0 = (uint32_t*)(So + 2 * BM);
    uint32_t* A1 = A0 + BM * S;
    uint32_t* Bs = A1 + BM * S;
    float* biasS = (float*)(Bs + (CIN / 2) * 66);
    const int tid = threadIdx.x;
    const uint32_t a0b = cvta_smem(A0), a1b = cvta_smem(A1);
    const int w = tid >> 5, lane = tid & 31, g = lane >> 2, tig = lane & 3;

    int p0 = blockIdx.x * T * BM;
    if (p0 >= P) return;
    if (pairs[(pbase + p0) * 2 + 1] >= n_out) return;  // prefix early-exit

    load_Bh<CIN>(Bs, Wk, tid);
    if (tid < 64) biasS[tid] = biask ? biask[tid] : 0.f;

    if (tid < BM) {
        int p = p0 + tid;
        if (p < P) {
            const int* pr = pairs + (pbase + p) * 2;
            Si[tid] = pr[0]; So[tid] = pr[1];
        } else { Si[tid] = n_zero; So[tid] = n_out; }
    }
    __syncthreads();
    gather_async<CIN, G2, false>(a0b, f1, f2, Si, 0, 0, 0, tid); CP_COMMIT();
    gather_async<CIN, G2, false>(a1b, f1, f2, Si, 0, 0, 1, tid); CP_COMMIT();

    int buf = 0;
    for (int t = 0; ; t++) {
        // hoist current tile's out-indices before any index-buffer overwrite
        const int* Sob = So + buf * BM;
        const int o0 = Sob[16 * w + g];
        const int o1 = Sob[16 * w + g + 8];

        int p0n = p0 + BM;
        bool nxt = (t + 1 < T) && (p0n < P) && (pairs[(pbase + p0n) * 2 + 1] < n_out);
        if (nxt && tid < BM) {
            int p = p0n + tid;
            int* Si2 = Si + (buf ^ 1) * BM;
            int* So2 = So + (buf ^ 1) * BM;
            if (p < P) {
                const int* pr = pairs + (pbase + p) * 2;
                Si2[tid] = pr[0]; So2[tid] = pr[1];
            } else { Si2[tid] = n_zero; So2[tid] = n_out; }
        }
        cp_wait<1>(); __syncthreads();
        float acc[8][4];
        acc_zero(acc);
        mma16<CIN>(A0, Bs, 0, w, g, tig, acc);
        __syncthreads();
        if (nxt) {
            gather_async<CIN, G2, false>(a0b, f1, f2, Si + (buf ^ 1) * BM, 0, 0, 0, tid);
            CP_COMMIT();
            cp_wait<1>();
        } else cp_wait<0>();
        __syncthreads();
        mma16<CIN>(A1, Bs, 1, w, g, tig, acc);
        __syncthreads();
        if (nxt) {
            gather_async<CIN, G2, false>(a1b, f1, f2, Si + (buf ^ 1) * BM, 0, 0, 1, tid);
            CP_COMMIT();
        }
        apply_bias_smem(acc, biasS, tig);
        if (o0 < n_out) scatter_add(out, o0, tig, acc, 0);
        if (o1 < n_out) scatter_add(out, o1, tig, acc, 1);
        if (!nxt) return;
        buf ^= 1; p0 = p0n;
    }
}

template <int CIN, int T, bool G2, bool UPMAP>
__global__ __launch_bounds__(256, 4) void spmm_rest(
    const __half* __restrict__ f1, const __half* __restrict__ f2,
    const int* __restrict__ pairs, const float* __restrict__ W,
    const float* __restrict__ bias, float* __restrict__ out,
    int P, int n_out, int n_zero, int kskip)
{
    int ky = blockIdx.y;
    int k = UPMAP ? c_upk[ky] : ((kskip >= 0 && ky >= kskip) ? ky + 1 : ky);
    rest_body<CIN, T, G2>(f1, f2, pairs, (long long)k * P,
                          W + (size_t)k * CIN * CO,
                          bias ? bias + k * CO : nullptr,
                          out, P, n_out, n_zero);
}

// merged conv13-rest + conv31-rest (grid.y = 16)
template <int T>
__global__ __launch_bounds__(256, 4) void spmm_rest2(
    const __half* __restrict__ f1,
    const int* __restrict__ pA, const int* __restrict__ pB,
    const float* __restrict__ WA, const float* __restrict__ WB,
    const float* __restrict__ bA, const float* __restrict__ bB,
    float* __restrict__ oA, float* __restrict__ oB,
    int P, int n_out, int n_zero)
{
    int ky = blockIdx.y;
    bool first = ky < 8;
    int kk = ky & 7;
    int k = kk + (kk >= 4);   // skip center offset 4
    rest_body<CO, T, false>(f1, nullptr, first ? pA : pB, (long long)k * P,
                            (first ? WA : WB) + (size_t)k * CO * CO,
                            (first ? bA : bB) + k * CO,
                            first ? oA : oB, P, n_out, n_zero);
}

// ---------------- elementwise / prep -----------------------------------------
__global__ void k_add_h(const float4* __restrict__ a, const float4* __restrict__ b,
                        __half2* __restrict__ o, int n4) {
    for (int i = blockIdx.x * blockDim.x + threadIdx.x; i < n4; i += gridDim.x * blockDim.x) {
        float4 x = a[i], y = b[i];
        o[2 * i]     = __floats2half2_rn(x.x + y.x, x.y + y.y);
        o[2 * i + 1] = __floats2half2_rn(x.z + y.z, x.w + y.w);
    }
}

__global__ void k_stats_act(const float* __restrict__ buf, __half* __restrict__ outh,
                            float* __restrict__ stats, int n) {
    __shared__ float ss[CO], sq[CO];
    int tid = threadIdx.x;
    if (tid < CO) { ss[tid] = 0.f; sq[tid] = 0.f; }
    __syncthreads();
    float s = 0.f, q = 0.f;
    int c = tid & (CO - 1);
    int total = n * CO;
    for (int idx = blockIdx.x * blockDim.x + tid; idx < total; idx += gridDim.x * blockDim.x) {
        float v = buf[idx];
        v = (v > 0.f) ? v : 0.01f * v;
        outh[idx] = __float2half_rn(v);
        s += v; q += v * v;
    }
    atomicAdd(&ss[c], s);
    atomicAdd(&sq[c], q);
    __syncthreads();
    if (tid < CO) {
        atomicAdd(&stats[tid], ss[tid]);
        atomicAdd(&stats[CO + tid], sq[tid]);
    }
}

__global__ void k_stats2(const float* __restrict__ e1, const float* __restrict__ e2,
                         __half* __restrict__ e1h, __half* __restrict__ e2h,
                         float* __restrict__ stats, int n) {
    __shared__ float s[4 * CO];
    int tid = threadIdx.x;
    for (int i = tid; i < 4 * CO; i += 256) s[i] = 0.f;
    __syncthreads();
    float s1 = 0.f, q1 = 0.f, s2 = 0.f, q2 = 0.f;
    int c = tid & (CO - 1);
    int total = n * CO;
    for (int idx = blockIdx.x * blockDim.x + tid; idx < total; idx += gridDim.x * blockDim.x) {
        float v1 = e1[idx], v2 = e2[idx];
        e1h[idx] = __float2half_rn(v1);
        e2h[idx] = __float2half_rn(v2);
        s1 += v1; q1 += v1 * v1;
        s2 += v2; q2 += v2 * v2;
    }
    atomicAdd(&s[c], s1);
    atomicAdd(&s[CO + c], q1);
    atomicAdd(&s[2 * CO + c], s2);
    atomicAdd(&s[3 * CO + c], q2);
    __syncthreads();
    if (tid < CO) {
        atomicAdd(&stats[2 * CO + tid], s[tid]);
        atomicAdd(&stats[3 * CO + tid], s[CO + tid]);
        atomicAdd(&stats[4 * CO + tid], s[2 * CO + tid]);
        atomicAdd(&stats[5 * CO + tid], s[3 * CO + tid]);
    }
}

// fused finalize + fold for BOTH W1 and W2 in one launch (18 blocks):
// block k<9 -> W1 -> W1s/b1s ; block k>=9 -> W2 -> W2s/b2s
__global__ void k_prep2(const float* __restrict__ W1, const float* __restrict__ W2,
                        const float* __restrict__ stats,
                        const float* __restrict__ g, const float* __restrict__ b,
                        float* __restrict__ W1s, float* __restrict__ W2s,
                        float* __restrict__ b1s, float* __restrict__ b2s, float invN) {
    int blk = blockIdx.x;
    bool first = blk < 9;
    int k = first ? blk : blk - 9;
    const float* W = first ? W1 : W2;
    float* Ws = first ? W1s : W2s;
    float* bias = first ? b1s : b2s;
    int tid = threadIdx.x;
    __shared__ float sc[64], off[64];
    __shared__ float pb[4][64];
    if (tid < 64) {
        float mean = stats[tid] * invN;
        float var  = stats[CO + tid] * invN - mean * mean;
        float s = g[tid] * rsqrtf(var + 1e-5f);
        sc[tid] = s;
        off[tid] = b[tid] - mean * s;
    }
    __syncthreads();
    const float* Wk = W + (size_t)k * 4096;
    float* Wsk = Ws + (size_t)k * 4096;
    float acc = 0.f;
    int n = tid & 63, cg = tid >> 6;
    #pragma unroll
    for (int cc = 0; cc < 16; cc++) {
        int c = cg * 16 + cc;
        float wv = Wk[c * 64 + n];
        Wsk[c * 64 + n] = sc[c] * wv;
        acc += off[c] * wv;
    }
    pb[cg][n] = acc;
    __syncthreads();
    if (tid < 64) bias[k * 64 + tid] = pb[0][tid] + pb[1][tid] + pb[2][tid] + pb[3][tid];
}

// fused finalize2 + upsample fold (layers 1,2 from stats[128..383]).
// RACE-FREE: per-layer offsets go to disjoint arrays, summed after the sync.
__global__ void k_prep_up(const float* __restrict__ Wu, const float* __restrict__ stats,
                          const float* __restrict__ g1, const float* __restrict__ b1,
                          const float* __restrict__ g2, const float* __restrict__ b2,
                          float* __restrict__ Bst, float* __restrict__ bias, float invN) {
    int k = blockIdx.x;
    int tid = threadIdx.x;
    __shared__ float sc1[64], sc2[64], off1[64], off2[64];
    __shared__ float pb[4][64];
    if (tid < 128) {
        int layer = tid >> 6, c = tid & 63;
        const float* st = stats + (1 + layer) * 2 * CO;
        float mean = st[c] * invN;
        float var  = st[CO + c] * invN - mean * mean;
        float s = (layer ? g2[c] : g1[c]) * rsqrtf(var + 1e-5f);
        float o = (layer ? b2[c] : b1[c]) - mean * s;
        if (layer) { sc2[c] = s; off2[c] = o; }
        else       { sc1[c] = s; off1[c] = o; }
    }
    __syncthreads();
    const float* Wk = Wu + (size_t)k * 4096;
    float* Bk = Bst + (size_t)k * 8192;
    float acc = 0.f;
    int n = tid & 63, cg = tid >> 6;
    #pragma unroll
    for (int cc = 0; cc < 16; cc++) {
        int c = cg * 16 + cc;
        float wv = Wk[c * 64 + n];
        Bk[c * 64 + n] = sc1[c] * wv;
        Bk[4096 + c * 64 + n] = sc2[c] * wv;
        acc += (off1[c] + off2[c]) * wv;
    }
    pb[cg][n] = acc;
    __syncthreads();
    if (tid < 64) bias[k * 64 + tid] = pb[0][tid] + pb[1][tid] + pb[2][tid] + pb[3][tid];
}

__global__ void k_dummy() {}

// ---------------- launch ------------------------------------------------------
extern "C" void kernel_launch(void* const* d_in, const int* in_sizes, int n_in,
                              void* d_out, int out_size) {
    const float* fx  = (const float*)d_in[0];
    const float* fs  = (const float*)d_in[1];
    const float* Wt  = (const float*)d_in[2];
    const float* W1  = (const float*)d_in[3];
    const float* W2  = (const float*)d_in[4];
    const float* Wu  = (const float*)d_in[5];
    const float* g0  = (const float*)d_in[6];
    const float* b0  = (const float*)d_in[7];
    const float* g1  = (const float*)d_in[8];
    const float* b1  = (const float*)d_in[9];
    const float* g2  = (const float*)d_in[10];
    const float* b2  = (const float*)d_in[11];
    const int*   p33 = (const int*)d_in[12];
    const int*   p13 = (const int*)d_in[13];
    const int*   p31 = (const int*)d_in[14];
    const int*   pup = (const int*)d_in[15];
    float* outp = (float*)d_out;

    __half *xh, *upAh, *e1h, *e2h;
    float *upA, *e1, *e2, *stats, *w1s, *w2s, *bup, *b1s, *b2s, *bupb;
    cudaGetSymbolAddress((void**)&xh,    g_xh);
    cudaGetSymbolAddress((void**)&upA,   g_upA);
    cudaGetSymbolAddress((void**)&upAh,  g_upAh);
    cudaGetSymbolAddress((void**)&e1,    g_e1);
    cudaGetSymbolAddress((void**)&e2,    g_e2);
    cudaGetSymbolAddress((void**)&e1h,   g_e1h);
    cudaGetSymbolAddress((void**)&e2h,   g_e2h);
    cudaGetSymbolAddress((void**)&stats, g_stats);
    cudaGetSymbolAddress((void**)&w1s,   g_W1s);
    cudaGetSymbolAddress((void**)&w2s,   g_W2s);
    cudaGetSymbolAddress((void**)&bup,   g_Bup);
    cudaGetSymbolAddress((void**)&b1s,   g_b1s);
    cudaGetSymbolAddress((void**)&b2s,   g_b2s);
    cudaGetSymbolAddress((void**)&bupb,  g_bup);

    // smem bytes: A = 2*BM*S, B = NW*(CIN/2)*66, bias NW*64, rest adds 4*BM idx
    const int SM_R128  = (4 * BM + 2 * BM * 36 + 64 * 66 + 64) * 4;   // 56064
    const int SM_R64   = (4 * BM + 2 * BM * 20 + 32 * 66 + 64) * 4;   // 31232
    const int SM_C128  = (2 * BM * 36 + 64 * 66 + 64) * 4;            // 54016
    const int SM_C64x2 = (2 * BM * 20 + 2 * 32 * 66 + 128) * 4;       // 37888
    const int SM_UP    = (2 * BM * 36 + 2 * 64 * 66 + 128) * 4;       // 71168

    cudaFuncSetAttribute((const void*)spmm_center<CI128, 1, 4, false>, cudaFuncAttributeMaxDynamicSharedMemorySize, SM_C128);
    cudaFuncSetAttribute((const void*)spmm_rest<CI128, 4, false, false>, cudaFuncAttributeMaxDynamicSharedMemorySize, SM_R128);
    cudaFuncSetAttribute((const void*)spmm_center<CO, 2, 4, false>, cudaFuncAttributeMaxDynamicSharedMemorySize, SM_C64x2);
    cudaFuncSetAttribute((const void*)spmm_rest2<4>, cudaFuncAttributeMaxDynamicSharedMemorySize, SM_R64);
    cudaFuncSetAttribute((const void*)spmm_center<CI128, 2, 4, true>, cudaFuncAttributeMaxDynamicSharedMemorySize, SM_UP);
    cudaFuncSetAttribute((const void*)spmm_rest<CI128, 4, true, true>, cudaFuncAttributeMaxDynamicSharedMemorySize, SM_R128);

    cudaMemsetAsync(stats, 0, 6 * CO * sizeof(float));

    // (1) xh = fp16(feats_x + feats_skip)
    k_add_h<<<2048, 256>>>((const float4*)fx, (const float4*)fs, (__half2*)xh, NCV * CI128 / 4);

    // (2) conv1 center: upA = xh @ Wt[13] (plain stores; rest adds after)
    spmm_center<CI128, 1, 4, false><<<NB, 256, SM_C128>>>(
        xh, nullptr, Wt + (size_t)13 * CI128 * CO, nullptr, nullptr, nullptr,
        upA, nullptr, NCV);

    // (3) dummy — keeps conv1-rest at ncu capture slot #4
    k_dummy<<<1, 32>>>();

    // (4) conv1 rest: 26 offsets atomic into upA
    spmm_rest<CI128, 4, false, false><<<dim3(NB, 26), 256, SM_R128>>>(
        xh, nullptr, p33, Wt, nullptr, upA, NCV, NCV, NCV, 13);

    // (5) leaky + stats -> upAh
    k_stats_act<<<1024, 256>>>(upA, upAh, stats, NCV);

    // (6) fused finalize+fold bn0 into W1 AND W2 (one launch)
    k_prep2<<<18, 256>>>(W1, W2, stats, g0, b0, w1s, w2s, b1s, b2s, 1.0f / NCV);

    // (7) conv13/31 centers: e1 = upAh @ W1s[4] + b1s[4]; e2 likewise
    spmm_center<CO, 2, 4, false><<<NB, 256, SM_C64x2>>>(
        upAh, nullptr, w1s + (size_t)4 * CO * CO, w2s + (size_t)4 * CO * CO,
        b1s + 4 * CO, b2s + 4 * CO, e1, e2, NCV);

    // (8) conv13/31 rest merged (16 jobs)
    spmm_rest2<4><<<dim3(NB, 16), 256, SM_R64>>>(
        upAh, p13, p31, w1s, w2s, b1s, b2s, e1, e2, NCV, NCV, NCV);

    // (9) e1/e2 stats -> e1h/e2h
    k_stats2<<<1024, 256>>>(e1, e2, e1h, e2h, stats, NCV);

    // (10) fused finalize2 + fold bn1/bn2 into stacked upsample weights
    k_prep_up<<<27, 256>>>(Wu, stats, g1, b1, g2, b2, bup, bupb, 1.0f / NCV);

    // (11) upsample identity offsets 13 & 26: dense stores covering all of d_out
    spmm_center<CI128, 2, 4, true><<<NB, 256, SM_UP>>>(
        e1h, e2h, bup + (size_t)13 * 8192, bup + (size_t)26 * 8192,
        bupb + 13 * CO, bupb + 26 * CO, outp, outp + (size_t)NCV * CO, NCV);

    // (12) upsample: the 7 possibly-nonempty sparse offsets, atomic into d_out
    spmm_rest<CI128, 4, true, true><<<dim3(NB, 7), 256, SM_R128>>>(
        e1h, e2h, pup, bup, bupb, outp, NCV, NFV, NCV, 0);
}

// round 17
// speedup vs baseline: 1.1401x; 1.0838x over previous
#include <cuda_runtime.h>
#include <cuda_fp16.h>
#include <cstdint>

#define NCV 120000
#define NFV 240000
#define CI128 128
#define CO 64
#define BM 128
#define NB 235
#define FULL 0xffffffffu

// ---------------- scratch (device globals) ---------------------------------
__device__ __half g_xh[(NCV + 1) * CI128];
__device__ float  g_upA[(NCV + 1) * CO];
__device__ __half g_upAh[(NCV + 1) * CO];
__device__ float  g_e1[(NCV + 1) * CO];
__device__ float  g_e2[(NCV + 1) * CO];
__device__ __half g_e1h[(NCV + 1) * CO];
__device__ __half g_e2h[(NCV + 1) * CO];
__device__ float  g_stats[6 * CO];
__device__ float  g_W1s[9 * CO * CO];
__device__ float  g_W2s[9 * CO * CO];
__device__ float  g_Bup[27 * 2 * CO * CO];   // stacked [s1*Wu ; s2*Wu]
__device__ float  g_b1s[9 * CO];
__device__ float  g_b2s[9 * CO];
__device__ float  g_bup[27 * CO];

__constant__ int c_upk[7] = {0, 2, 6, 8, 18, 20, 24};

// ---------------- helpers ---------------------------------------------------
__device__ __forceinline__ void mma_f16(float* d, uint32_t a0, uint32_t a1,
                                        uint32_t a2, uint32_t a3,
                                        uint32_t b0, uint32_t b1) {
    asm volatile(
        "mma.sync.aligned.m16n8k16.row.col.f32.f16.f16.f32 "
        "{%0,%1,%2,%3}, {%4,%5,%6,%7}, {%8,%9}, {%0,%1,%2,%3};"
        : "+f"(d[0]), "+f"(d[1]), "+f"(d[2]), "+f"(d[3])
        : "r"(a0), "r"(a1), "r"(a2), "r"(a3), "r"(b0), "r"(b1));
}
__device__ __forceinline__ void red_add_v4(float* addr, float x, float y, float z, float w) {
    asm volatile("red.global.add.v4.f32 [%0], {%1, %2, %3, %4};"
                 :: "l"(addr), "f"(x), "f"(y), "f"(z), "f"(w) : "memory");
}
__device__ __forceinline__ uint32_t cvta_smem(const void* p) {
    uint32_t a;
    asm("{ .reg .u64 t; cvta.to.shared.u64 t, %1; cvt.u32.u64 %0, t; }" : "=r"(a) : "l"(p));
    return a;
}
__device__ __forceinline__ void cp_async16(uint32_t dst, const void* src) {
    asm volatile("cp.async.ca.shared.global [%0], [%1], 16;" :: "r"(dst), "l"(src));
}
#define CP_COMMIT() asm volatile("cp.async.commit_group;" ::: "memory")
template <int N>
__device__ __forceinline__ void cp_wait() {
    asm volatile("cp.async.wait_group %0;" :: "n"(N) : "memory");
}

// ---------------- MMA building blocks ---------------------------------------
// B smem: permuted half2 rows (one row per k-pair), stride 66 words.
// Output-column mapping chosen so thread (g,tig) owns 4 CONTIGUOUS output
// columns per instance-pair: instance m, native col j -> actual col
//   A(m,j) = 16*(m>>1) + 4*(j>>1) + 2*(m&1) + (j&1)
// Storage position for actual col n (thread g supplies native col j=g of
// instance m): pos = 8*g + m with
//   m = 2*(n>>4) + ((n>>1)&1),  g = 2*((n>>2)&3) + (n&1)
template <int CIN>
__device__ __forceinline__ void load_Bh(uint32_t* Bs, const float* Wk, int tid) {
    #pragma unroll
    for (int i = tid; i < (CIN / 2) * 64; i += 256) {
        int n = i & 63, kp = i >> 6;
        float w0 = Wk[(2 * kp) * 64 + n];
        float w1 = Wk[(2 * kp + 1) * 64 + n];
        __half2 h = __floats2half2_rn(w0, w1);
        int pos = 8 * (2 * ((n >> 2) & 3) + (n & 1)) + 2 * (n >> 4) + ((n >> 1) & 1);
        Bs[kp * 66 + pos] = *(uint32_t*)&h;
    }
}

// async gather of one K-half chunk (halves). Row data = KH halves = KH*2 bytes.
// G2: half0 <- f1, half1 <- f2 (rows of KH halves). else: f1 rows of CIN halves.
template <int CIN, bool G2, bool IDENT>
__device__ __forceinline__ void gather_async(uint32_t abase, const __half* f1, const __half* f2,
                                             const int* Si, int p0, int nclamp,
                                             int half_idx, int tid) {
    constexpr int KH = CIN / 2;
    constexpr int U = KH / 8;                 // 16B units per row-chunk (8 or 4)
    constexpr int S = (KH == 64) ? 36 : 20;   // row stride in words
    constexpr int RSTEP = 256 / U;
    const int u = tid & (U - 1);
    const int rr0 = tid / U;
    #pragma unroll
    for (int r = rr0; r < BM; r += RSTEP) {
        int row;
        if (IDENT) { row = p0 + r; if (row > nclamp) row = nclamp; }
        else row = Si[r];
        const __half* src;
        if (G2) src = (half_idx ? f2 : f1) + (size_t)row * KH + u * 8;
        else    src = f1 + (size_t)row * CIN + half_idx * KH + u * 8;
        cp_async16(abase + (uint32_t)(r * S * 4 + u * 16), src);
    }
}

// MMA over one K-half chunk. A half2 words stride S (CTA-wide buffer; warp w
// owns rows 16w..16w+15); Bw points at the weight matrix (k-pair rows, stride
// 66, permuted n). Addressing identical to previous rounds; only the meaning
// of instance columns changed (handled in load_Bh / scatter / bias).
template <int CIN>
__device__ __forceinline__ void mma16(const uint32_t* Aw, const uint32_t* Bw,
                                      int half_idx, int w, int g, int tig,
                                      float acc[8][4]) {
    constexpr int KH = CIN / 2;
    constexpr int S = (KH == 64) ? 36 : 20;
    const int kb = half_idx * (KH / 2);       // k-pair row base of this chunk
    const uint32_t* r0 = Aw + (16 * w + g) * S;
    const uint32_t* r1 = Aw + (16 * w + g + 8) * S;
    #pragma unroll
    for (int ks = 0; ks < KH / 16; ks++) {
        const int kw = ks * 8;
        uint32_t a0 = r0[kw + tig];
        uint32_t a1 = r1[kw + tig];
        uint32_t a2 = r0[kw + tig + 4];
        uint32_t a3 = r1[kw + tig + 4];
        const uint2* b0p = (const uint2*)(Bw + (kb + kw + tig) * 66 + g * 8);
        const uint2* b1p = (const uint2*)(Bw + (kb + kw + tig + 4) * 66 + g * 8);
        #pragma unroll
        for (int c2 = 0; c2 < 4; c2++) {
            uint2 u0 = b0p[c2], u1 = b1p[c2];
            mma_f16(acc[2 * c2],     a0, a1, a2, a3, u0.x, u1.x);
            mma_f16(acc[2 * c2 + 1], a0, a1, a2, a3, u0.y, u1.y);
        }
    }
}

__device__ __forceinline__ void acc_zero(float acc[8][4]) {
    #pragma unroll
    for (int c = 0; c < 8; c++) { acc[c][0] = acc[c][1] = acc[c][2] = acc[c][3] = 0.f; }
}
// thread (g,tig) owns cols 16q+4tig..+3 (q=0..3): instance 2q -> +0,+1;
// instance 2q+1 -> +2,+3.
__device__ __forceinline__ void apply_bias_smem(float acc[8][4], const float* bS, int tig) {
    #pragma unroll
    for (int q = 0; q < 4; q++) {
        float4 b = *(const float4*)(bS + 16 * q + 4 * tig);
        acc[2 * q][0] += b.x;     acc[2 * q][1] += b.y;
        acc[2 * q + 1][0] += b.z; acc[2 * q + 1][1] += b.w;
        acc[2 * q][2] += b.x;     acc[2 * q][3] += b.y;
        acc[2 * q + 1][2] += b.z; acc[2 * q + 1][3] += b.w;
    }
}
__device__ __forceinline__ void scatter_add(float* out, int o, int tig,
                                            const float acc[8][4], int half) {
    float* d = out + (size_t)o * CO + 4 * tig;
    #pragma unroll
    for (int q = 0; q < 4; q++)
        red_add_v4(d + 16 * q, acc[2 * q][2 * half], acc[2 * q][2 * half + 1],
                   acc[2 * q + 1][2 * half], acc[2 * q + 1][2 * half + 1]);
}
__device__ __forceinline__ void scatter_st(float* out, int o, int tig,
                                           const float acc[8][4], int half) {
    float4* d = (float4*)(out + (size_t)o * CO + 4 * tig);
    #pragma unroll
    for (int q = 0; q < 4; q++)
        d[4 * q] = make_float4(acc[2 * q][2 * half], acc[2 * q][2 * half + 1],
                               acc[2 * q + 1][2 * half], acc[2 * q + 1][2 * half + 1]);
}

// ---------------- center kernel: identity rows, plain stores, pipelined -----
template <int CIN, int NW, int T, bool G2>
__global__ __launch_bounds__(256, (NW == 1) ? 4 : 2) void spmm_center(
    const __half* __restrict__ f1, const __half* __restrict__ f2,
    const float* __restrict__ W0, const float* __restrict__ W1b,
    const float* __restrict__ bias0, const float* __restrict__ bias1,
    float* __restrict__ out0, float* __restrict__ out1, int n)
{
    constexpr int KH = CIN / 2;
    constexpr int S = (KH == 64) ? 36 : 20;
    constexpr int BW = (CIN / 2) * 66;       // words per weight matrix
    extern __shared__ uint32_t sm[];
    uint32_t* A0 = sm;
    uint32_t* A1 = A0 + BM * S;
    uint32_t* Bs = A1 + BM * S;
    float* biasS = (float*)(Bs + NW * BW);
    const int tid = threadIdx.x;
    const uint32_t a0b = cvta_smem(A0), a1b = cvta_smem(A1);
    const int w = tid >> 5, lane = tid & 31, g = lane >> 2, tig = lane & 3;

    load_Bh<CIN>(Bs, W0, tid);
    if (NW == 2) load_Bh<CIN>(Bs + BW, W1b, tid);
    if (tid < 64) biasS[tid] = bias0 ? bias0[tid] : 0.f;
    if (NW == 2 && tid >= 64 && tid < 128) biasS[tid] = bias1 ? bias1[tid - 64] : 0.f;

    int p0 = blockIdx.x * T * BM;
    if (p0 >= n) return;
    gather_async<CIN, G2, true>(a0b, f1, f2, nullptr, p0, n, 0, tid); CP_COMMIT();
    gather_async<CIN, G2, true>(a1b, f1, f2, nullptr, p0, n, 1, tid); CP_COMMIT();

    for (int t = 0; ; t++) {
        int p0n = p0 + BM;
        bool nxt = (t + 1 < T) && (p0n < n);
        cp_wait<1>(); __syncthreads();
        float acc[8][4], accB[8][4];
        acc_zero(acc);
        mma16<CIN>(A0, Bs, 0, w, g, tig, acc);
        if (NW == 2) { acc_zero(accB); mma16<CIN>(A0, Bs + BW, 0, w, g, tig, accB); }
        __syncthreads();
        if (nxt) {
            gather_async<CIN, G2, true>(a0b, f1, f2, nullptr, p0n, n, 0, tid); CP_COMMIT();
            cp_wait<1>();
        } else cp_wait<0>();
        __syncthreads();
        mma16<CIN>(A1, Bs, 1, w, g, tig, acc);
        if (NW == 2) mma16<CIN>(A1, Bs + BW, 1, w, g, tig, accB);
        __syncthreads();
        if (nxt) { gather_async<CIN, G2, true>(a1b, f1, f2, nullptr, p0n, n, 1, tid); CP_COMMIT(); }
        apply_bias_smem(acc, biasS, tig);
        int r0 = p0 + 16 * w + g;
        if (r0 < n) scatter_st(out0, r0, tig, acc, 0);
        if (r0 + 8 < n) scatter_st(out0, r0 + 8, tig, acc, 1);
        if (NW == 2) {
            apply_bias_smem(accB, biasS + 64, tig);
            if (r0 < n) scatter_st(out1, r0, tig, accB, 0);
            if (r0 + 8 < n) scatter_st(out1, r0 + 8, tig, accB, 1);
        }
        if (!nxt) return;
        p0 = p0n;
    }
}

// ---------------- rest body: pair gather, atomic scatter, pipelined ---------
template <int CIN, int T, bool G2>
__device__ __forceinline__ void rest_body(
    const __half* __restrict__ f1, const __half* __restrict__ f2,
    const int* __restrict__ pairs, long long pbase,
    const float* __restrict__ Wk, const float* __restrict__ biask,
    float* __restrict__ out, int P, int n_out, int n_zero)
{
    constexpr int KH = CIN / 2;
    constexpr int S = (KH == 64) ? 36 : 20;
    extern __shared__ uint32_t sm[];
    int* Si = (int*)sm;                 // [2][BM]
    int* So = Si + 2 * BM;              // [2][BM]
    uint32_t* A0 = (uint32_t*)(So + 2 * BM);
    uint32_t* A1 = A0 + BM * S;
    uint32_t* Bs = A1 + BM * S;
    float* biasS = (float*)(Bs + (CIN / 2) * 66);
    const int tid = threadIdx.x;
    const uint32_t a0b = cvta_smem(A0), a1b = cvta_smem(A1);
    const int w = tid >> 5, lane = tid & 31, g = lane >> 2, tig = lane & 3;

    int p0 = blockIdx.x * T * BM;
    if (p0 >= P) return;
    if (pairs[(pbase + p0) * 2 + 1] >= n_out) return;  // prefix early-exit

    load_Bh<CIN>(Bs, Wk, tid);
    if (tid < 64) biasS[tid] = biask ? biask[tid] : 0.f;

    if (tid < BM) {
        int p = p0 + tid;
        if (p < P) {
            const int* pr = pairs + (pbase + p) * 2;
            Si[tid] = pr[0]; So[tid] = pr[1];
        } else { Si[tid] = n_zero; So[tid] = n_out; }
    }
    __syncthreads();
    gather_async<CIN, G2, false>(a0b, f1, f2, Si, 0, 0, 0, tid); CP_COMMIT();
    gather_async<CIN, G2, false>(a1b, f1, f2, Si, 0, 0, 1, tid); CP_COMMIT();

    int buf = 0;
    for (int t = 0; ; t++) {
        // hoist current tile's out-indices before any index-buffer overwrite
        const int* Sob = So + buf * BM;
        const int o0 = Sob[16 * w + g];
        const int o1 = Sob[16 * w + g + 8];

        int p0n = p0 + BM;
        bool nxt = (t + 1 < T) && (p0n < P) && (pairs[(pbase + p0n) * 2 + 1] < n_out);
        if (nxt && tid < BM) {
            int p = p0n + tid;
            int* Si2 = Si + (buf ^ 1) * BM;
            int* So2 = So + (buf ^ 1) * BM;
            if (p < P) {
                const int* pr = pairs + (pbase + p) * 2;
                Si2[tid] = pr[0]; So2[tid] = pr[1];
            } else { Si2[tid] = n_zero; So2[tid] = n_out; }
        }
        cp_wait<1>(); __syncthreads();
        float acc[8][4];
        acc_zero(acc);
        mma16<CIN>(A0, Bs, 0, w, g, tig, acc);
        __syncthreads();
        if (nxt) {
            gather_async<CIN, G2, false>(a0b, f1, f2, Si + (buf ^ 1) * BM, 0, 0, 0, tid);
            CP_COMMIT();
            cp_wait<1>();
        } else cp_wait<0>();
        __syncthreads();
        mma16<CIN>(A1, Bs, 1, w, g, tig, acc);
        __syncthreads();
        if (nxt) {
            gather_async<CIN, G2, false>(a1b, f1, f2, Si + (buf ^ 1) * BM, 0, 0, 1, tid);
            CP_COMMIT();
        }
        apply_bias_smem(acc, biasS, tig);
        if (o0 < n_out) scatter_add(out, o0, tig, acc, 0);
        if (o1 < n_out) scatter_add(out, o1, tig, acc, 1);
        if (!nxt) return;
        buf ^= 1; p0 = p0n;
    }
}

template <int CIN, int T, bool G2, bool UPMAP>
__global__ __launch_bounds__(256, 4) void spmm_rest(
    const __half* __restrict__ f1, const __half* __restrict__ f2,
    const int* __restrict__ pairs, const float* __restrict__ W,
    const float* __restrict__ bias, float* __restrict__ out,
    int P, int n_out, int n_zero, int kskip)
{
    int ky = blockIdx.y;
    int k = UPMAP ? c_upk[ky] : ((kskip >= 0 && ky >= kskip) ? ky + 1 : ky);
    rest_body<CIN, T, G2>(f1, f2, pairs, (long long)k * P,
                          W + (size_t)k * CIN * CO,
                          bias ? bias + k * CO : nullptr,
                          out, P, n_out, n_zero);
}

// merged conv13-rest + conv31-rest (grid.y = 16)
template <int T>
__global__ __launch_bounds__(256, 4) void spmm_rest2(
    const __half* __restrict__ f1,
    const int* __restrict__ pA, const int* __restrict__ pB,
    const float* __restrict__ WA, const float* __restrict__ WB,
    const float* __restrict__ bA, const float* __restrict__ bB,
    float* __restrict__ oA, float* __restrict__ oB,
    int P, int n_out, int n_zero)
{
    int ky = blockIdx.y;
    bool first = ky < 8;
    int kk = ky & 7;
    int k = kk + (kk >= 4);   // skip center offset 4
    rest_body<CO, T, false>(f1, nullptr, first ? pA : pB, (long long)k * P,
                            (first ? WA : WB) + (size_t)k * CO * CO,
                            (first ? bA : bB) + k * CO,
                            first ? oA : oB, P, n_out, n_zero);
}

// ---------------- elementwise / prep -----------------------------------------
__global__ void k_add_h(const float4* __restrict__ a, const float4* __restrict__ b,
                        __half2* __restrict__ o, int n4) {
    for (int i = blockIdx.x * blockDim.x + threadIdx.x; i < n4; i += gridDim.x * blockDim.x) {
        float4 x = a[i], y = b[i];
        o[2 * i]     = __floats2half2_rn(x.x + y.x, x.y + y.y);
        o[2 * i + 1] = __floats2half2_rn(x.z + y.z, x.w + y.w);
    }
}

__global__ void k_stats_act(const float* __restrict__ buf, __half* __restrict__ outh,
                            float* __restrict__ stats, int n) {
    __shared__ float ss[CO], sq[CO];
    int tid = threadIdx.x;
    if (tid < CO) { ss[tid] = 0.f; sq[tid] = 0.f; }
    __syncthreads();
    float s = 0.f, q = 0.f;
    int c = tid & (CO - 1);
    int total = n * CO;
    for (int idx = blockIdx.x * blockDim.x + tid; idx < total; idx += gridDim.x * blockDim.x) {
        float v = buf[idx];
        v = (v > 0.f) ? v : 0.01f * v;
        outh[idx] = __float2half_rn(v);
        s += v; q += v * v;
    }
    atomicAdd(&ss[c], s);
    atomicAdd(&sq[c], q);
    __syncthreads();
    if (tid < CO) {
        atomicAdd(&stats[tid], ss[tid]);
        atomicAdd(&stats[CO + tid], sq[tid]);
    }
}

__global__ void k_stats2(const float* __restrict__ e1, const float* __restrict__ e2,
                         __half* __restrict__ e1h, __half* __restrict__ e2h,
                         float* __restrict__ stats, int n) {
    __shared__ float s[4 * CO];
    int tid = threadIdx.x;
    for (int i = tid; i < 4 * CO; i += 256) s[i] = 0.f;
    __syncthreads();
    float s1 = 0.f, q1 = 0.f, s2 = 0.f, q2 = 0.f;
    int c = tid & (CO - 1);
    int total = n * CO;
    for (int idx = blockIdx.x * blockDim.x + tid; idx < total; idx += gridDim.x * blockDim.x) {
        float v1 = e1[idx], v2 = e2[idx];
        e1h[idx] = __float2half_rn(v1);
        e2h[idx] = __float2half_rn(v2);
        s1 += v1; q1 += v1 * v1;
        s2 += v2; q2 += v2 * v2;
    }
    atomicAdd(&s[c], s1);
    atomicAdd(&s[CO + c], q1);
    atomicAdd(&s[2 * CO + c], s2);
    atomicAdd(&s[3 * CO + c], q2);
    __syncthreads();
    if (tid < CO) {
        atomicAdd(&stats[2 * CO + tid], s[tid]);
        atomicAdd(&stats[3 * CO + tid], s[CO + tid]);
        atomicAdd(&stats[4 * CO + tid], s[2 * CO + tid]);
        atomicAdd(&stats[5 * CO + tid], s[3 * CO + tid]);
    }
}

// fused finalize + fold for BOTH W1 and W2 in one launch (18 blocks)
__global__ void k_prep2(const float* __restrict__ W1, const float* __restrict__ W2,
                        const float* __restrict__ stats,
                        const float* __restrict__ g, const float* __restrict__ b,
                        float* __restrict__ W1s, float* __restrict__ W2s,
                        float* __restrict__ b1s, float* __restrict__ b2s, float invN) {
    int blk = blockIdx.x;
    bool first = blk < 9;
    int k = first ? blk : blk - 9;
    const float* W = first ? W1 : W2;
    float* Ws = first ? W1s : W2s;
    float* bias = first ? b1s : b2s;
    int tid = threadIdx.x;
    __shared__ float sc[64], off[64];
    __shared__ float pb[4][64];
    if (tid < 64) {
        float mean = stats[tid] * invN;
        float var  = stats[CO + tid] * invN - mean * mean;
        float s = g[tid] * rsqrtf(var + 1e-5f);
        sc[tid] = s;
        off[tid] = b[tid] - mean * s;
    }
    __syncthreads();
    const float* Wk = W + (size_t)k * 4096;
    float* Wsk = Ws + (size_t)k * 4096;
    float acc = 0.f;
    int n = tid & 63, cg = tid >> 6;
    #pragma unroll
    for (int cc = 0; cc < 16; cc++) {
        int c = cg * 16 + cc;
        float wv = Wk[c * 64 + n];
        Wsk[c * 64 + n] = sc[c] * wv;
        acc += off[c] * wv;
    }
    pb[cg][n] = acc;
    __syncthreads();
    if (tid < 64) bias[k * 64 + tid] = pb[0][tid] + pb[1][tid] + pb[2][tid] + pb[3][tid];
}

// fused finalize2 + upsample fold (layers 1,2 from stats[128..383]); race-free.
__global__ void k_prep_up(const float* __restrict__ Wu, const float* __restrict__ stats,
                          const float* __restrict__ g1, const float* __restrict__ b1,
                          const float* __restrict__ g2, const float* __restrict__ b2,
                          float* __restrict__ Bst, float* __restrict__ bias, float invN) {
    int k = blockIdx.x;
    int tid = threadIdx.x;
    __shared__ float sc1[64], sc2[64], off1[64], off2[64];
    __shared__ float pb[4][64];
    if (tid < 128) {
        int layer = tid >> 6, c = tid & 63;
        const float* st = stats + (1 + layer) * 2 * CO;
        float mean = st[c] * invN;
        float var  = st[CO + c] * invN - mean * mean;
        float s = (layer ? g2[c] : g1[c]) * rsqrtf(var + 1e-5f);
        float o = (layer ? b2[c] : b1[c]) - mean * s;
        if (layer) { sc2[c] = s; off2[c] = o; }
        else       { sc1[c] = s; off1[c] = o; }
    }
    __syncthreads();
    const float* Wk = Wu + (size_t)k * 4096;
    float* Bk = Bst + (size_t)k * 8192;
    float acc = 0.f;
    int n = tid & 63, cg = tid >> 6;
    #pragma unroll
    for (int cc = 0; cc < 16; cc++) {
        int c = cg * 16 + cc;
        float wv = Wk[c * 64 + n];
        Bk[c * 64 + n] = sc1[c] * wv;
        Bk[4096 + c * 64 + n] = sc2[c] * wv;
        acc += (off1[c] + off2[c]) * wv;
    }
    pb[cg][n] = acc;
    __syncthreads();
    if (tid < 64) bias[k * 64 + tid] = pb[0][tid] + pb[1][tid] + pb[2][tid] + pb[3][tid];
}

__global__ void k_dummy() {}

// ---------------- launch ------------------------------------------------------
extern "C" void kernel_launch(void* const* d_in, const int* in_sizes, int n_in,
                              void* d_out, int out_size) {
    const float* fx  = (const float*)d_in[0];
    const float* fs  = (const float*)d_in[1];
    const float* Wt  = (const float*)d_in[2];
    const float* W1  = (const float*)d_in[3];
    const float* W2  = (const float*)d_in[4];
    const float* Wu  = (const float*)d_in[5];
    const float* g0  = (const float*)d_in[6];
    const float* b0  = (const float*)d_in[7];
    const float* g1  = (const float*)d_in[8];
    const float* b1  = (const float*)d_in[9];
    const float* g2  = (const float*)d_in[10];
    const float* b2  = (const float*)d_in[11];
    const int*   p33 = (const int*)d_in[12];
    const int*   p13 = (const int*)d_in[13];
    const int*   p31 = (const int*)d_in[14];
    const int*   pup = (const int*)d_in[15];
    float* outp = (float*)d_out;

    __half *xh, *upAh, *e1h, *e2h;
    float *upA, *e1, *e2, *stats, *w1s, *w2s, *bup, *b1s, *b2s, *bupb;
    cudaGetSymbolAddress((void**)&xh,    g_xh);
    cudaGetSymbolAddress((void**)&upA,   g_upA);
    cudaGetSymbolAddress((void**)&upAh,  g_upAh);
    cudaGetSymbolAddress((void**)&e1,    g_e1);
    cudaGetSymbolAddress((void**)&e2,    g_e2);
    cudaGetSymbolAddress((void**)&e1h,   g_e1h);
    cudaGetSymbolAddress((void**)&e2h,   g_e2h);
    cudaGetSymbolAddress((void**)&stats, g_stats);
    cudaGetSymbolAddress((void**)&w1s,   g_W1s);
    cudaGetSymbolAddress((void**)&w2s,   g_W2s);
    cudaGetSymbolAddress((void**)&bup,   g_Bup);
    cudaGetSymbolAddress((void**)&b1s,   g_b1s);
    cudaGetSymbolAddress((void**)&b2s,   g_b2s);
    cudaGetSymbolAddress((void**)&bupb,  g_bup);

    // smem bytes: A = 2*BM*S, B = NW*(CIN/2)*66, bias NW*64, rest adds 4*BM idx
    const int SM_R128  = (4 * BM + 2 * BM * 36 + 64 * 66 + 64) * 4;   // 56064
    const int SM_R64   = (4 * BM + 2 * BM * 20 + 32 * 66 + 64) * 4;   // 31232
    const int SM_C128  = (2 * BM * 36 + 64 * 66 + 64) * 4;            // 54016
    const int SM_C64x2 = (2 * BM * 20 + 2 * 32 * 66 + 128) * 4;       // 37888
    const int SM_UP    = (2 * BM * 36 + 2 * 64 * 66 + 128) * 4;       // 71168

    cudaFuncSetAttribute((const void*)spmm_center<CI128, 1, 4, false>, cudaFuncAttributeMaxDynamicSharedMemorySize, SM_C128);
    cudaFuncSetAttribute((const void*)spmm_rest<CI128, 4, false, false>, cudaFuncAttributeMaxDynamicSharedMemorySize, SM_R128);
    cudaFuncSetAttribute((const void*)spmm_center<CO, 2, 4, false>, cudaFuncAttributeMaxDynamicSharedMemorySize, SM_C64x2);
    cudaFuncSetAttribute((const void*)spmm_rest2<4>, cudaFuncAttributeMaxDynamicSharedMemorySize, SM_R64);
    cudaFuncSetAttribute((const void*)spmm_center<CI128, 2, 4, true>, cudaFuncAttributeMaxDynamicSharedMemorySize, SM_UP);
    cudaFuncSetAttribute((const void*)spmm_rest<CI128, 4, true, true>, cudaFuncAttributeMaxDynamicSharedMemorySize, SM_R128);

    cudaMemsetAsync(stats, 0, 6 * CO * sizeof(float));

    // (1) xh = fp16(feats_x + feats_skip)
    k_add_h<<<2048, 256>>>((const float4*)fx, (const float4*)fs, (__half2*)xh, NCV * CI128 / 4);

    // (2) conv1 center: upA = xh @ Wt[13] (plain stores; rest adds after)
    spmm_center<CI128, 1, 4, false><<<NB, 256, SM_C128>>>(
        xh, nullptr, Wt + (size_t)13 * CI128 * CO, nullptr, nullptr, nullptr,
        upA, nullptr, NCV);

    // (3) dummy — keeps conv1-rest at ncu capture slot #4
    k_dummy<<<1, 32>>>();

    // (4) conv1 rest: 26 offsets atomic into upA
    spmm_rest<CI128, 4, false, false><<<dim3(NB, 26), 256, SM_R128>>>(
        xh, nullptr, p33, Wt, nullptr, upA, NCV, NCV, NCV, 13);

    // (5) leaky + stats -> upAh
    k_stats_act<<<1024, 256>>>(upA, upAh, stats, NCV);

    // (6) fused finalize+fold bn0 into W1 AND W2 (one launch)
    k_prep2<<<18, 256>>>(W1, W2, stats, g0, b0, w1s, w2s, b1s, b2s, 1.0f / NCV);

    // (7) conv13/31 centers: e1 = upAh @ W1s[4] + b1s[4]; e2 likewise
    spmm_center<CO, 2, 4, false><<<NB, 256, SM_C64x2>>>(
        upAh, nullptr, w1s + (size_t)4 * CO * CO, w2s + (size_t)4 * CO * CO,
        b1s + 4 * CO, b2s + 4 * CO, e1, e2, NCV);

    // (8) conv13/31 rest merged (16 jobs)
    spmm_rest2<4><<<dim3(NB, 16), 256, SM_R64>>>(
        upAh, p13, p31, w1s, w2s, b1s, b2s, e1, e2, NCV, NCV, NCV);

    // (9) e1/e2 stats -> e1h/e2h
    k_stats2<<<1024, 256>>>(e1, e2, e1h, e2h, stats, NCV);

    // (10) fused finalize2 + fold bn1/bn2 into stacked upsample weights
    k_prep_up<<<27, 256>>>(Wu, stats, g1, b1, g2, b2, bup, bupb, 1.0f / NCV);

    // (11) upsample identity offsets 13 & 26: dense stores covering all of d_out
    spmm_center<CI128, 2, 4, true><<<NB, 256, SM_UP>>>(
        e1h, e2h, bup + (size_t)13 * 8192, bup + (size_t)26 * 8192,
        bupb + 13 * CO, bupb + 26 * CO, outp, outp + (size_t)NCV * CO, NCV);

    // (12) upsample: the 7 possibly-nonempty sparse offsets, atomic into d_out
    spmm_rest<CI128, 4, true, true><<<dim3(NB, 7), 256, SM_R128>>>(
        e1h, e2h, pup, bup, bupb, outp, NCV, NFV, NCV, 0);
}